// round 2
// baseline (speedup 1.0000x reference)
#include <cuda_runtime.h>
#include <cstdint>

#define N_TOK 8192
#define DDIM  1024
#define NB    512
#define HDIM  4096
#define TOPK  8

// smem row padding: 132 floats (528B) keeps 16B alignment for vector LDS while
// reducing transposed-store conflicts from 4-way to 2-way.
#define SPAD 132

// ---------------- scratch (static device allocations; no cudaMalloc) ----------------
static __device__ float g_ln[(size_t)N_TOK * DDIM];       // 32 MB
static __device__ float g_alpha[(size_t)N_TOK * NB];      // 16 MB
static __device__ float g_H[(size_t)N_TOK * HDIM];        // 128 MB
static __device__ float g_U[(size_t)NB * DDIM];           // 2 MB
static __device__ float g_V[(size_t)NB * DDIM];           // 2 MB
static __device__ int   g_idx[(size_t)N_TOK * TOPK];
static __device__ float g_Z[(size_t)N_TOK * TOPK];

// ---------------- packed f32x2 helpers (Blackwell dual-lane FP32) ----------------
__device__ __forceinline__ unsigned long long pack2(float a, float b) {
    unsigned long long r;
    asm("mov.b64 %0, {%1,%2};" : "=l"(r) : "f"(a), "f"(b));
    return r;
}
__device__ __forceinline__ void unpack2(unsigned long long v, float &a, float &b) {
    asm("mov.b64 {%0,%1}, %2;" : "=f"(a), "=f"(b) : "l"(v));
}
__device__ __forceinline__ void ffma2(unsigned long long &d, unsigned long long a,
                                      unsigned long long b) {
    asm("fma.rn.f32x2 %0, %1, %2, %0;" : "+l"(d) : "l"(a), "l"(b));
}

// ---------------- NT GEMM: C[m,n] = sum_k A[m,k]*B[n,k]  (A:[M,K], B:[N,K] row-major)
// EPI: 0 = exact GELU, 1 = +bias, clip +-10, softplus, 2 = accumulate into existing C
template <int EPI>
__global__ __launch_bounds__(256, 2)
void gemm_nt_kernel(const float *__restrict__ A, const float *__restrict__ B,
                    const float *__restrict__ bias, float *__restrict__ C,
                    int M, int N, int K) {
    __shared__ __align__(16) float As[16][SPAD];
    __shared__ __align__(16) float Bs[16][SPAD];
    const int tid = threadIdx.x;
    const int tx = tid & 15;   // N direction (16 threads)
    const int ty = tid >> 4;   // M direction (16 threads)
    const int bm = blockIdx.y * 128;
    const int bn = blockIdx.x * 128;
    const int lr = tid >> 2;           // 0..63 row within tile
    const int lc = (tid & 3) << 2;     // k offset: 0,4,8,12

    const float *Ap = A + (size_t)(bm + lr) * K + lc;
    const float *Bp = B + (size_t)(bn + lr) * K + lc;

    unsigned long long acc[8][4];
#pragma unroll
    for (int i = 0; i < 8; i++)
#pragma unroll
        for (int j = 0; j < 4; j++) acc[i][j] = 0ULL;

    // software pipeline: prefetch tile kt=0
    float4 a0 = *(const float4 *)Ap;
    float4 a1 = *(const float4 *)(Ap + (size_t)64 * K);
    float4 b0 = *(const float4 *)Bp;
    float4 b1 = *(const float4 *)(Bp + (size_t)64 * K);

    for (int kt = 0; kt < K; kt += 16) {
        As[lc + 0][lr] = a0.x; As[lc + 1][lr] = a0.y; As[lc + 2][lr] = a0.z; As[lc + 3][lr] = a0.w;
        As[lc + 0][lr + 64] = a1.x; As[lc + 1][lr + 64] = a1.y; As[lc + 2][lr + 64] = a1.z; As[lc + 3][lr + 64] = a1.w;
        Bs[lc + 0][lr] = b0.x; Bs[lc + 1][lr] = b0.y; Bs[lc + 2][lr] = b0.z; Bs[lc + 3][lr] = b0.w;
        Bs[lc + 0][lr + 64] = b1.x; Bs[lc + 1][lr + 64] = b1.y; Bs[lc + 2][lr + 64] = b1.z; Bs[lc + 3][lr + 64] = b1.w;
        __syncthreads();

        // prefetch next tile while computing on smem
        if (kt + 16 < K) {
            Ap += 16; Bp += 16;
            a0 = *(const float4 *)Ap;
            a1 = *(const float4 *)(Ap + (size_t)64 * K);
            b0 = *(const float4 *)Bp;
            b1 = *(const float4 *)(Bp + (size_t)64 * K);
        }

#pragma unroll
        for (int kk = 0; kk < 16; kk++) {
            ulonglong2 bv0 = *reinterpret_cast<const ulonglong2 *>(&Bs[kk][tx * 4]);
            ulonglong2 bv1 = *reinterpret_cast<const ulonglong2 *>(&Bs[kk][64 + tx * 4]);
            float4 m0 = *reinterpret_cast<const float4 *>(&As[kk][ty * 8]);
            float4 m1 = *reinterpret_cast<const float4 *>(&As[kk][ty * 8 + 4]);
            float mr[8] = {m0.x, m0.y, m0.z, m0.w, m1.x, m1.y, m1.z, m1.w};
#pragma unroll
            for (int i = 0; i < 8; i++) {
                unsigned long long a2 = pack2(mr[i], mr[i]);
                ffma2(acc[i][0], a2, bv0.x);
                ffma2(acc[i][1], a2, bv0.y);
                ffma2(acc[i][2], a2, bv1.x);
                ffma2(acc[i][3], a2, bv1.y);
            }
        }
        __syncthreads();
    }

#pragma unroll
    for (int i = 0; i < 8; i++) {
        float v[8];
        unpack2(acc[i][0], v[0], v[1]);
        unpack2(acc[i][1], v[2], v[3]);
        unpack2(acc[i][2], v[4], v[5]);
        unpack2(acc[i][3], v[6], v[7]);
        const int row = bm + ty * 8 + i;
        const int c0 = bn + tx * 4;
        const int c1 = bn + 64 + tx * 4;
        if (EPI == 0) {
#pragma unroll
            for (int j = 0; j < 8; j++) {
                float xv = v[j];
                v[j] = 0.5f * xv * (1.0f + erff(xv * 0.7071067811865476f));
            }
        } else if (EPI == 1) {
#pragma unroll
            for (int j = 0; j < 8; j++) {
                int col = (j < 4) ? (c0 + j) : (c1 + (j - 4));
                float r = v[j] + bias[col];
                r = fminf(fmaxf(r, -10.0f), 10.0f);
                v[j] = fmaxf(r, 0.0f) + log1pf(expf(-fabsf(r)));  // stable softplus
            }
        } else {
            float4 o0 = *(const float4 *)(C + (size_t)row * N + c0);
            float4 o1 = *(const float4 *)(C + (size_t)row * N + c1);
            v[0] += o0.x; v[1] += o0.y; v[2] += o0.z; v[3] += o0.w;
            v[4] += o1.x; v[5] += o1.y; v[6] += o1.z; v[7] += o1.w;
        }
        *(float4 *)(C + (size_t)row * N + c0) = make_float4(v[0], v[1], v[2], v[3]);
        *(float4 *)(C + (size_t)row * N + c1) = make_float4(v[4], v[5], v[6], v[7]);
    }
}

// ---------------- LayerNorm: one block (256 thr) per token ----------------
__global__ __launch_bounds__(256)
void ln_kernel(const float *__restrict__ x, const float *__restrict__ g,
               const float *__restrict__ b, float *__restrict__ out) {
    __shared__ float sm1[8], sm2[8];
    const int n = blockIdx.x, tid = threadIdx.x;
    const float4 xr = *(const float4 *)(x + (size_t)n * DDIM + tid * 4);
    float s = xr.x + xr.y + xr.z + xr.w;
    float s2 = xr.x * xr.x + xr.y * xr.y + xr.z * xr.z + xr.w * xr.w;
    const int lane = tid & 31, w = tid >> 5;
#pragma unroll
    for (int o = 16; o; o >>= 1) {
        s += __shfl_xor_sync(~0u, s, o);
        s2 += __shfl_xor_sync(~0u, s2, o);
    }
    if (lane == 0) { sm1[w] = s; sm2[w] = s2; }
    __syncthreads();
    float ts = 0.f, ts2 = 0.f;
#pragma unroll
    for (int i = 0; i < 8; i++) { ts += sm1[i]; ts2 += sm2[i]; }
    const float mu = ts * (1.0f / DDIM);
    const float var = ts2 * (1.0f / DDIM) - mu * mu;
    const float rstd = rsqrtf(var + 1e-5f);
    const float4 g4 = *(const float4 *)(g + tid * 4);
    const float4 b4 = *(const float4 *)(b + tid * 4);
    float4 o;
    o.x = (xr.x - mu) * rstd * g4.x + b4.x;
    o.y = (xr.y - mu) * rstd * g4.y + b4.y;
    o.z = (xr.z - mu) * rstd * g4.z + b4.z;
    o.w = (xr.w - mu) * rstd * g4.w + b4.w;
    *(float4 *)(out + (size_t)n * DDIM + tid * 4) = o;
}

// ---------------- unit-normalize U and V rows: 1024 blocks ----------------
__global__ __launch_bounds__(256)
void unit_kernel(const float *__restrict__ rU, const float *__restrict__ rV) {
    __shared__ float sm[8];
    const int r = blockIdx.x, tid = threadIdx.x;
    const float *src;
    float *dst;
    if (r < NB) { src = rU + (size_t)r * DDIM; dst = g_U + (size_t)r * DDIM; }
    else        { src = rV + (size_t)(r - NB) * DDIM; dst = g_V + (size_t)(r - NB) * DDIM; }
    const float4 xr = *(const float4 *)(src + tid * 4);
    float s2 = xr.x * xr.x + xr.y * xr.y + xr.z * xr.z + xr.w * xr.w;
    const int lane = tid & 31, w = tid >> 5;
#pragma unroll
    for (int o = 16; o; o >>= 1) s2 += __shfl_xor_sync(~0u, s2, o);
    if (lane == 0) sm[w] = s2;
    __syncthreads();
    float t = 0.f;
#pragma unroll
    for (int i = 0; i < 8; i++) t += sm[i];
    const float sc = 1.0f / fmaxf(sqrtf(t), 1e-6f);
    float4 o;
    o.x = xr.x * sc; o.y = xr.y * sc; o.z = xr.z * sc; o.w = xr.w * sc;
    *(float4 *)(dst + tid * 4) = o;
}

// ---------------- top-8 + Z: one warp per token ----------------
__global__ __launch_bounds__(256)
void topk_kernel() {
    const int warp = (blockIdx.x * blockDim.x + threadIdx.x) >> 5;
    const int lane = threadIdx.x & 31;
    const float *a = g_alpha + (size_t)warp * NB;
    float v[16];
#pragma unroll
    for (int s = 0; s < 16; s++) v[s] = a[lane + 32 * s];
    float phi[TOPK];
    int pid[TOPK];
    float S = 0.f;
#pragma unroll
    for (int k = 0; k < TOPK; k++) {
        float bv = -1e30f;
        int bi = 0;
#pragma unroll
        for (int s = 0; s < 16; s++) {
            int id = lane + 32 * s;
            if (v[s] > bv) { bv = v[s]; bi = id; }   // increasing id -> first max kept
        }
#pragma unroll
        for (int off = 16; off; off >>= 1) {
            float ov = __shfl_xor_sync(~0u, bv, off);
            int oi = __shfl_xor_sync(~0u, bi, off);
            if (ov > bv || (ov == bv && oi < bi)) { bv = ov; bi = oi; }
        }
        phi[k] = bv;
        pid[k] = bi;
        S += bv;
        if ((bi & 31) == lane) {
            const int slot = bi >> 5;
#pragma unroll
            for (int s = 0; s < 16; s++)
                if (s == slot) v[s] = -1e30f;
        }
    }
    const float t = tanhf(S);
    const float inv = 1.0f / (S + 1e-6f);
    if (lane == 0) {
#pragma unroll
        for (int k = 0; k < TOPK; k++) {
            g_Z[(size_t)warp * TOPK + k] = phi[k] * inv * t;
            g_idx[(size_t)warp * TOPK + k] = pid[k];
        }
    }
}

// ---------------- dynamic path: one block per token, writes gamma*dyn into out ----
__global__ __launch_bounds__(256)
void dyn_kernel(const float *__restrict__ x, const float *__restrict__ gamma,
                float *__restrict__ out) {
    __shared__ int srow[TOPK];
    __shared__ float sZ[TOPK];
    __shared__ float hred[TOPK][8];
    __shared__ float hk[TOPK];
    const int n = blockIdx.x, tid = threadIdx.x;
    if (tid < TOPK) {
        srow[tid] = g_idx[(size_t)n * TOPK + tid];
        sZ[tid] = g_Z[(size_t)n * TOPK + tid];
    }
    __syncthreads();
    const float4 xr = *(const float4 *)(x + (size_t)n * DDIM + tid * 4);
    const int lane = tid & 31, w = tid >> 5;
#pragma unroll
    for (int k = 0; k < TOPK; k++) {
        const float4 u = *(const float4 *)(g_U + (size_t)srow[k] * DDIM + tid * 4);
        float p = xr.x * u.x + xr.y * u.y + xr.z * u.z + xr.w * u.w;
#pragma unroll
        for (int o = 16; o; o >>= 1) p += __shfl_xor_sync(~0u, p, o);
        if (lane == 0) hred[k][w] = p;
    }
    __syncthreads();
    if (tid < TOPK) {
        float s = 0.f;
#pragma unroll
        for (int w2 = 0; w2 < 8; w2++) s += hred[tid][w2];
        hk[tid] = s * sZ[tid];
    }
    __syncthreads();
    float4 o = make_float4(0.f, 0.f, 0.f, 0.f);
#pragma unroll
    for (int k = 0; k < TOPK; k++) {
        const float4 vv = *(const float4 *)(g_V + (size_t)srow[k] * DDIM + tid * 4);
        const float c = hk[k];
        o.x += c * vv.x; o.y += c * vv.y; o.z += c * vv.z; o.w += c * vv.w;
    }
    const float4 g4 = *(const float4 *)(gamma + tid * 4);
    o.x *= g4.x; o.y *= g4.y; o.z *= g4.z; o.w *= g4.w;
    *(float4 *)(out + (size_t)n * DDIM + tid * 4) = o;
}

// ---------------- launch ----------------
extern "C" void kernel_launch(void *const *d_in, const int *in_sizes, int n_in,
                              void *d_out, int out_size) {
    (void)in_sizes; (void)n_in; (void)out_size;
    const float *x    = (const float *)d_in[0];
    const float *W1   = (const float *)d_in[1];
    const float *W2   = (const float *)d_in[2];
    const float *ln_g = (const float *)d_in[3];
    const float *ln_b = (const float *)d_in[4];
    const float *rW   = (const float *)d_in[5];
    const float *rb   = (const float *)d_in[6];
    const float *rU   = (const float *)d_in[7];
    const float *rV   = (const float *)d_in[8];
    const float *gamma = (const float *)d_in[9];
    float *out = (float *)d_out;

    void *p_ln_v, *p_alpha_v, *p_H_v;
    cudaGetSymbolAddress(&p_ln_v, g_ln);
    cudaGetSymbolAddress(&p_alpha_v, g_alpha);
    cudaGetSymbolAddress(&p_H_v, g_H);
    float *p_ln = (float *)p_ln_v;
    float *p_alpha = (float *)p_alpha_v;
    float *p_H = (float *)p_H_v;

    // router path
    ln_kernel<<<N_TOK, 256>>>(x, ln_g, ln_b, p_ln);
    unit_kernel<<<2 * NB, 256>>>(rU, rV);
    gemm_nt_kernel<1><<<dim3(NB / 128, N_TOK / 128), 256>>>(p_ln, rW, rb, p_alpha,
                                                            N_TOK, NB, DDIM);
    topk_kernel<<<N_TOK / 8, 256>>>();
    dyn_kernel<<<N_TOK, 256>>>(x, gamma, out);   // writes gamma*dyn into out

    // static path (gemm2 accumulates onto dyn already in out)
    gemm_nt_kernel<0><<<dim3(HDIM / 128, N_TOK / 128), 256>>>(x, W1, nullptr, p_H,
                                                              N_TOK, HDIM, DDIM);
    gemm_nt_kernel<2><<<dim3(DDIM / 128, N_TOK / 128), 256>>>(p_H, W2, nullptr, out,
                                                              N_TOK, DDIM, HDIM);
}

// round 10
// speedup vs baseline: 1.6045x; 1.6045x over previous
#include <cuda_runtime.h>
#include <cuda_bf16.h>
#include <cstdint>

#define N_TOK 8192
#define DDIM  1024
#define NB    512
#define HDIM  4096
#define TOPK  8

// ===================== scratch (static device allocations) =====================
static __device__ __nv_bfloat16 g_xhi[(size_t)N_TOK * DDIM];
static __device__ __nv_bfloat16 g_xlo[(size_t)N_TOK * DDIM];
static __device__ __nv_bfloat16 g_w1hi[(size_t)HDIM * DDIM];
static __device__ __nv_bfloat16 g_w1lo[(size_t)HDIM * DDIM];
static __device__ __nv_bfloat16 g_w2hi[(size_t)DDIM * HDIM];
static __device__ __nv_bfloat16 g_w2lo[(size_t)DDIM * HDIM];
static __device__ __nv_bfloat16 g_Hhi[(size_t)N_TOK * HDIM];
static __device__ __nv_bfloat16 g_Hlo[(size_t)N_TOK * HDIM];
static __device__ float g_ln[(size_t)N_TOK * DDIM];
static __device__ float g_alpha[(size_t)N_TOK * NB];
static __device__ float g_U[(size_t)NB * DDIM];
static __device__ float g_V[(size_t)NB * DDIM];
static __device__ int   g_idx[(size_t)N_TOK * TOPK];
static __device__ float g_Z[(size_t)N_TOK * TOPK];

// ===================== sm_80-era primitives (valid on base sm_103 target) =====
__device__ __forceinline__ uint32_t smem_u32(const void *p) {
    uint32_t a;
    asm("{ .reg .u64 t; cvta.to.shared.u64 t, %1; cvt.u32.u64 %0, t; }" : "=r"(a) : "l"(p));
    return a;
}
__device__ __forceinline__ void cp_async16(uint32_t smem, const void *gmem) {
    asm volatile("cp.async.cg.shared.global [%0], [%1], 16;" :: "r"(smem), "l"(gmem)
                 : "memory");
}
__device__ __forceinline__ void cp_commit() {
    asm volatile("cp.async.commit_group;" ::: "memory");
}
template <int N>
__device__ __forceinline__ void cp_wait() {
    asm volatile("cp.async.wait_group %0;" :: "n"(N) : "memory");
}
__device__ __forceinline__ void ldm_x4(uint32_t *r, uint32_t addr) {
    asm volatile("ldmatrix.sync.aligned.m8n8.x4.shared.b16 {%0,%1,%2,%3}, [%4];"
                 : "=r"(r[0]), "=r"(r[1]), "=r"(r[2]), "=r"(r[3]) : "r"(addr));
}
__device__ __forceinline__ void mma16816(float *c, const uint32_t *a, uint32_t b0,
                                         uint32_t b1) {
    asm volatile(
        "mma.sync.aligned.m16n8k16.row.col.f32.bf16.bf16.f32 "
        "{%0,%1,%2,%3}, {%4,%5,%6,%7}, {%8,%9}, {%0,%1,%2,%3};"
        : "+f"(c[0]), "+f"(c[1]), "+f"(c[2]), "+f"(c[3])
        : "r"(a[0]), "r"(a[1]), "r"(a[2]), "r"(a[3]), "r"(b0), "r"(b1));
}

// SMEM geometry: per operand tile 128 rows x 32 bf16, rows padded to 80 bytes.
// 80B stride => ldmatrix 8-address phases hit bank-groups {0,5,2,7,4,1,6,3}: conflict-free.
#define ROWB       80
#define OP_BYTES   (128 * ROWB)        // 10240
#define STG_BYTES  (4 * OP_BYTES)      // 40960 (Ahi, Alo, Bhi, Blo)
#define GEMM_SMEM  (2 * STG_BYTES)     // 81920, double-buffered

// ===================== mma.sync GEMM (NT, K-major), 128x128 tile, k-chunk 32
// 3-term split-bf16: C = Ahi*Bhi + Ahi*Blo + Alo*Bhi  (fp32 register accumulate)
// EPI: 0 = GELU -> split bf16 store (OHi/OLo)    (GEMM1)
//      2 = Cout += D                             (GEMM2)
template <int EPI>
__global__ __launch_bounds__(256, 2)
void gemm_mma(const __nv_bfloat16 *__restrict__ Ahi, const __nv_bfloat16 *__restrict__ Alo,
              const __nv_bfloat16 *__restrict__ Bhi, const __nv_bfloat16 *__restrict__ Blo,
              float *__restrict__ Cout,
              __nv_bfloat16 *__restrict__ OHi, __nv_bfloat16 *__restrict__ OLo,
              int K, int ldc) {
    extern __shared__ __align__(1024) char smem[];
    const uint32_t sbase = smem_u32(smem);

    const int tid = threadIdx.x;
    const int wid = tid >> 5, lane = tid & 31;
    const int wm = wid & 1, wn = wid >> 1;          // 2 x 4 warp grid
    const int bm = blockIdx.y * 128, bn = blockIdx.x * 128;

    const __nv_bfloat16 *srcs[4] = {Ahi + (size_t)bm * K, Alo + (size_t)bm * K,
                                    Bhi + (size_t)bn * K, Blo + (size_t)bn * K};

    // per-stage global->smem: each thread moves 2 x 16B per operand
    const int c0r = tid >> 2, c0k = tid & 3;          // chunk id tid
    const int c1r = (tid + 256) >> 2, c1k = tid & 3;  // chunk id tid+256 (k part same)
    auto load_stage = [&](int kc, int buf) {
        const uint32_t sb = sbase + buf * STG_BYTES;
#pragma unroll
        for (int t = 0; t < 4; t++) {
            cp_async16(sb + t * OP_BYTES + c0r * ROWB + c0k * 16,
                       srcs[t] + (size_t)c0r * K + kc + c0k * 8);
            cp_async16(sb + t * OP_BYTES + c1r * ROWB + c1k * 16,
                       srcs[t] + (size_t)c1r * K + kc + c1k * 8);
        }
        cp_commit();
    };

    // ldmatrix per-lane address parts: row = lane&15 within 16-row tile, +8 k-cols for hi half
    const int lrow = lane & 15;
    const uint32_t lkoff = (uint32_t)(lane >> 4) * 16;  // +8 bf16 in k

    float acc[4][4][4];
#pragma unroll
    for (int mi = 0; mi < 4; mi++)
#pragma unroll
        for (int ni = 0; ni < 4; ni++)
#pragma unroll
            for (int j = 0; j < 4; j++) acc[mi][ni][j] = 0.f;

    const int S = K >> 5;
    load_stage(0, 0);

    for (int s = 0; s < S; s++) {
        if (s + 1 < S) { load_stage((s + 1) << 5, (s + 1) & 1); cp_wait<1>(); }
        else           { cp_wait<0>(); }
        __syncthreads();

        const uint32_t sb = sbase + (s & 1) * STG_BYTES;
        const uint32_t aHiB = sb + 0 * OP_BYTES + (wm * 64 + lrow) * ROWB + lkoff;
        const uint32_t aLoB = sb + 1 * OP_BYTES + (wm * 64 + lrow) * ROWB + lkoff;
        const uint32_t bHiB = sb + 2 * OP_BYTES + (wn * 32 + lrow) * ROWB + lkoff;
        const uint32_t bLoB = sb + 3 * OP_BYTES + (wn * 32 + lrow) * ROWB + lkoff;

#pragma unroll
        for (int ks = 0; ks < 2; ks++) {
            const uint32_t ko = ks * 32;  // 16 bf16 = 32 bytes
            uint32_t bh[2][4], bl[2][4];
            ldm_x4(bh[0], bHiB + ko);             // n 0..15
            ldm_x4(bh[1], bHiB + 16 * ROWB + ko); // n 16..31
            ldm_x4(bl[0], bLoB + ko);
            ldm_x4(bl[1], bLoB + 16 * ROWB + ko);
#pragma unroll
            for (int mi = 0; mi < 4; mi++) {
                uint32_t a[4];
                ldm_x4(a, aHiB + mi * 16 * ROWB + ko);
#pragma unroll
                for (int ni = 0; ni < 4; ni++)
                    mma16816(acc[mi][ni], a, bh[ni >> 1][ni & 1], bh[ni >> 1][(ni & 1) + 2]);
#pragma unroll
                for (int ni = 0; ni < 4; ni++)
                    mma16816(acc[mi][ni], a, bl[ni >> 1][ni & 1], bl[ni >> 1][(ni & 1) + 2]);
                ldm_x4(a, aLoB + mi * 16 * ROWB + ko);
#pragma unroll
                for (int ni = 0; ni < 4; ni++)
                    mma16816(acc[mi][ni], a, bh[ni >> 1][ni & 1], bh[ni >> 1][(ni & 1) + 2]);
            }
        }
        __syncthreads();
    }

    // ===== epilogue: frag (mi,ni): rows g, g+8; cols tg*2, tg*2+1 =====
    const int g = lane >> 2, tg = lane & 3;
#pragma unroll
    for (int mi = 0; mi < 4; mi++) {
#pragma unroll
        for (int ni = 0; ni < 4; ni++) {
            const int r0 = bm + wm * 64 + mi * 16 + g;
            const int r1 = r0 + 8;
            const int col = bn + wn * 32 + ni * 8 + tg * 2;
            float *c = acc[mi][ni];
            if (EPI == 0) {
#pragma unroll
                for (int pair = 0; pair < 2; pair++) {
                    const int row = pair ? r1 : r0;
                    float v0 = c[pair * 2], v1 = c[pair * 2 + 1];
                    float g0 = 0.5f * v0 * (1.0f + erff(v0 * 0.7071067811865476f));
                    float g1 = 0.5f * v1 * (1.0f + erff(v1 * 0.7071067811865476f));
                    __nv_bfloat16 h0 = __float2bfloat16_rn(g0);
                    __nv_bfloat16 h1 = __float2bfloat16_rn(g1);
                    __nv_bfloat162 hh; hh.x = h0; hh.y = h1;
                    *(__nv_bfloat162 *)(OHi + (size_t)row * ldc + col) = hh;
                    *(__nv_bfloat162 *)(OLo + (size_t)row * ldc + col) =
                        __floats2bfloat162_rn(g0 - __bfloat162float(h0),
                                              g1 - __bfloat162float(h1));
                }
            } else {
                float2 o0 = *(float2 *)(Cout + (size_t)r0 * ldc + col);
                float2 o1 = *(float2 *)(Cout + (size_t)r1 * ldc + col);
                o0.x += c[0]; o0.y += c[1];
                o1.x += c[2]; o1.y += c[3];
                *(float2 *)(Cout + (size_t)r0 * ldc + col) = o0;
                *(float2 *)(Cout + (size_t)r1 * ldc + col) = o1;
            }
        }
    }
}

// ===================== f32x2 SGEMM for router (proven round-2 path) =====================
__device__ __forceinline__ unsigned long long pack2(float a, float b) {
    unsigned long long r;
    asm("mov.b64 %0, {%1,%2};" : "=l"(r) : "f"(a), "f"(b));
    return r;
}
__device__ __forceinline__ void unpack2(unsigned long long v, float &a, float &b) {
    asm("mov.b64 {%0,%1}, %2;" : "=f"(a), "=f"(b) : "l"(v));
}
__device__ __forceinline__ void ffma2(unsigned long long &d, unsigned long long a,
                                      unsigned long long b) {
    asm("fma.rn.f32x2 %0, %1, %2, %0;" : "+l"(d) : "l"(a), "l"(b));
}

__global__ __launch_bounds__(256, 2)
void router_gemm(const float *__restrict__ A, const float *__restrict__ B,
                 const float *__restrict__ bias, float *__restrict__ C,
                 int N, int K) {
    __shared__ float As[16][128];
    __shared__ float Bs[16][128];
    const int tid = threadIdx.x;
    const int tx = tid & 15;
    const int ty = tid >> 4;
    const int bm = blockIdx.y * 128;
    const int bn = blockIdx.x * 128;
    const int lr = tid >> 2;
    const int lc = (tid & 3) << 2;

    const float *Ap = A + (size_t)(bm + lr) * K + lc;
    const float *Bp = B + (size_t)(bn + lr) * K + lc;

    unsigned long long acc[8][4];
#pragma unroll
    for (int i = 0; i < 8; i++)
#pragma unroll
        for (int j = 0; j < 4; j++) acc[i][j] = 0ULL;

    for (int kt = 0; kt < K; kt += 16) {
        float4 a0 = *(const float4 *)Ap;
        float4 a1 = *(const float4 *)(Ap + (size_t)64 * K);
        float4 b0 = *(const float4 *)Bp;
        float4 b1 = *(const float4 *)(Bp + (size_t)64 * K);
        As[lc + 0][lr] = a0.x; As[lc + 1][lr] = a0.y; As[lc + 2][lr] = a0.z; As[lc + 3][lr] = a0.w;
        As[lc + 0][lr + 64] = a1.x; As[lc + 1][lr + 64] = a1.y; As[lc + 2][lr + 64] = a1.z; As[lc + 3][lr + 64] = a1.w;
        Bs[lc + 0][lr] = b0.x; Bs[lc + 1][lr] = b0.y; Bs[lc + 2][lr] = b0.z; Bs[lc + 3][lr] = b0.w;
        Bs[lc + 0][lr + 64] = b1.x; Bs[lc + 1][lr + 64] = b1.y; Bs[lc + 2][lr + 64] = b1.z; Bs[lc + 3][lr + 64] = b1.w;
        __syncthreads();
#pragma unroll
        for (int kk = 0; kk < 16; kk++) {
            ulonglong2 bv0 = *reinterpret_cast<const ulonglong2 *>(&Bs[kk][tx * 4]);
            ulonglong2 bv1 = *reinterpret_cast<const ulonglong2 *>(&Bs[kk][64 + tx * 4]);
            float4 m0 = *reinterpret_cast<const float4 *>(&As[kk][ty * 8]);
            float4 m1 = *reinterpret_cast<const float4 *>(&As[kk][ty * 8 + 4]);
            float mr[8] = {m0.x, m0.y, m0.z, m0.w, m1.x, m1.y, m1.z, m1.w};
#pragma unroll
            for (int i = 0; i < 8; i++) {
                unsigned long long a2 = pack2(mr[i], mr[i]);
                ffma2(acc[i][0], a2, bv0.x);
                ffma2(acc[i][1], a2, bv0.y);
                ffma2(acc[i][2], a2, bv1.x);
                ffma2(acc[i][3], a2, bv1.y);
            }
        }
        __syncthreads();
        Ap += 16;
        Bp += 16;
    }

#pragma unroll
    for (int i = 0; i < 8; i++) {
        float v[8];
        unpack2(acc[i][0], v[0], v[1]);
        unpack2(acc[i][1], v[2], v[3]);
        unpack2(acc[i][2], v[4], v[5]);
        unpack2(acc[i][3], v[6], v[7]);
        const int row = bm + ty * 8 + i;
        const int c0 = bn + tx * 4;
        const int c1 = bn + 64 + tx * 4;
#pragma unroll
        for (int j = 0; j < 8; j++) {
            int col = (j < 4) ? (c0 + j) : (c1 + (j - 4));
            float r = v[j] + bias[col];
            r = fminf(fmaxf(r, -10.0f), 10.0f);
            v[j] = fmaxf(r, 0.0f) + log1pf(expf(-fabsf(r)));  // stable softplus
        }
        *(float4 *)(C + (size_t)row * N + c0) = make_float4(v[0], v[1], v[2], v[3]);
        *(float4 *)(C + (size_t)row * N + c1) = make_float4(v[4], v[5], v[6], v[7]);
    }
}

// ===================== fp32 -> (hi, lo) bf16 split =====================
__global__ __launch_bounds__(256)
void split_kernel(const float *__restrict__ in, __nv_bfloat16 *__restrict__ hi,
                  __nv_bfloat16 *__restrict__ lo) {
    const size_t i4 = (size_t)blockIdx.x * 256 + threadIdx.x;
    const float4 v = *(const float4 *)(in + i4 * 4);
    __nv_bfloat16 h0 = __float2bfloat16_rn(v.x), h1 = __float2bfloat16_rn(v.y);
    __nv_bfloat16 h2 = __float2bfloat16_rn(v.z), h3 = __float2bfloat16_rn(v.w);
    __nv_bfloat162 a, b;
    a.x = h0; a.y = h1; b.x = h2; b.y = h3;
    *(__nv_bfloat162 *)(hi + i4 * 4) = a;
    *(__nv_bfloat162 *)(hi + i4 * 4 + 2) = b;
    *(__nv_bfloat162 *)(lo + i4 * 4) =
        __floats2bfloat162_rn(v.x - __bfloat162float(h0), v.y - __bfloat162float(h1));
    *(__nv_bfloat162 *)(lo + i4 * 4 + 2) =
        __floats2bfloat162_rn(v.z - __bfloat162float(h2), v.w - __bfloat162float(h3));
}

// ===================== LayerNorm (fp32 out, feeds router SGEMM) =====================
__global__ __launch_bounds__(256)
void ln_kernel(const float *__restrict__ x, const float *__restrict__ g,
               const float *__restrict__ b, float *__restrict__ out) {
    __shared__ float sm1[8], sm2[8];
    const int n = blockIdx.x, tid = threadIdx.x;
    const float4 xr = *(const float4 *)(x + (size_t)n * DDIM + tid * 4);
    float s = xr.x + xr.y + xr.z + xr.w;
    float s2 = xr.x * xr.x + xr.y * xr.y + xr.z * xr.z + xr.w * xr.w;
    const int lane = tid & 31, w = tid >> 5;
#pragma unroll
    for (int o = 16; o; o >>= 1) {
        s += __shfl_xor_sync(~0u, s, o);
        s2 += __shfl_xor_sync(~0u, s2, o);
    }
    if (lane == 0) { sm1[w] = s; sm2[w] = s2; }
    __syncthreads();
    float ts = 0.f, ts2 = 0.f;
#pragma unroll
    for (int i = 0; i < 8; i++) { ts += sm1[i]; ts2 += sm2[i]; }
    const float mu = ts * (1.0f / DDIM);
    const float var = ts2 * (1.0f / DDIM) - mu * mu;
    const float rstd = rsqrtf(var + 1e-5f);
    const float4 g4 = *(const float4 *)(g + tid * 4);
    const float4 b4 = *(const float4 *)(b + tid * 4);
    float4 o;
    o.x = (xr.x - mu) * rstd * g4.x + b4.x;
    o.y = (xr.y - mu) * rstd * g4.y + b4.y;
    o.z = (xr.z - mu) * rstd * g4.z + b4.z;
    o.w = (xr.w - mu) * rstd * g4.w + b4.w;
    *(float4 *)(out + (size_t)n * DDIM + tid * 4) = o;
}

// ===================== unit-normalize U and V rows =====================
__global__ __launch_bounds__(256)
void unit_kernel(const float *__restrict__ rU, const float *__restrict__ rV) {
    __shared__ float sm[8];
    const int r = blockIdx.x, tid = threadIdx.x;
    const float *src;
    float *dst;
    if (r < NB) { src = rU + (size_t)r * DDIM; dst = g_U + (size_t)r * DDIM; }
    else        { src = rV + (size_t)(r - NB) * DDIM; dst = g_V + (size_t)(r - NB) * DDIM; }
    const float4 xr = *(const float4 *)(src + tid * 4);
    float s2 = xr.x * xr.x + xr.y * xr.y + xr.z * xr.z + xr.w * xr.w;
    const int lane = tid & 31, w = tid >> 5;
#pragma unroll
    for (int o = 16; o; o >>= 1) s2 += __shfl_xor_sync(~0u, s2, o);
    if (lane == 0) sm[w] = s2;
    __syncthreads();
    float t = 0.f;
#pragma unroll
    for (int i = 0; i < 8; i++) t += sm[i];
    const float sc = 1.0f / fmaxf(sqrtf(t), 1e-6f);
    float4 o;
    o.x = xr.x * sc; o.y = xr.y * sc; o.z = xr.z * sc; o.w = xr.w * sc;
    *(float4 *)(dst + tid * 4) = o;
}

// ===================== top-8 + Z =====================
__global__ __launch_bounds__(256)
void topk_kernel() {
    const int warp = (blockIdx.x * blockDim.x + threadIdx.x) >> 5;
    const int lane = threadIdx.x & 31;
    const float *a = g_alpha + (size_t)warp * NB;
    float v[16];
#pragma unroll
    for (int s = 0; s < 16; s++) v[s] = a[lane + 32 * s];
    float phi[TOPK];
    int pid[TOPK];
    float S = 0.f;
#pragma unroll
    for (int k = 0; k < TOPK; k++) {
        float bv = -1e30f;
        int bi = 0;
#pragma unroll
        for (int s = 0; s < 16; s++) {
            int id = lane + 32 * s;
            if (v[s] > bv) { bv = v[s]; bi = id; }
        }
#pragma unroll
        for (int off = 16; off; off >>= 1) {
            float ov = __shfl_xor_sync(~0u, bv, off);
            int oi = __shfl_xor_sync(~0u, bi, off);
            if (ov > bv || (ov == bv && oi < bi)) { bv = ov; bi = oi; }
        }
        phi[k] = bv;
        pid[k] = bi;
        S += bv;
        if ((bi & 31) == lane) {
            const int slot = bi >> 5;
#pragma unroll
            for (int s = 0; s < 16; s++)
                if (s == slot) v[s] = -1e30f;
        }
    }
    const float t = tanhf(S);
    const float inv = 1.0f / (S + 1e-6f);
    if (lane == 0) {
#pragma unroll
        for (int k = 0; k < TOPK; k++) {
            g_Z[(size_t)warp * TOPK + k] = phi[k] * inv * t;
            g_idx[(size_t)warp * TOPK + k] = pid[k];
        }
    }
}

// ===================== dynamic path (writes gamma*dyn into out) =====================
__global__ __launch_bounds__(256)
void dyn_kernel(const float *__restrict__ x, const float *__restrict__ gamma,
                float *__restrict__ out) {
    __shared__ int srow[TOPK];
    __shared__ float sZ[TOPK];
    __shared__ float hred[TOPK][8];
    __shared__ float hk[TOPK];
    const int n = blockIdx.x, tid = threadIdx.x;
    if (tid < TOPK) {
        srow[tid] = g_idx[(size_t)n * TOPK + tid];
        sZ[tid] = g_Z[(size_t)n * TOPK + tid];
    }
    __syncthreads();
    const float4 xr = *(const float4 *)(x + (size_t)n * DDIM + tid * 4);
    const int lane = tid & 31, w = tid >> 5;
#pragma unroll
    for (int k = 0; k < TOPK; k++) {
        const float4 u = *(const float4 *)(g_U + (size_t)srow[k] * DDIM + tid * 4);
        float p = xr.x * u.x + xr.y * u.y + xr.z * u.z + xr.w * u.w;
#pragma unroll
        for (int o = 16; o; o >>= 1) p += __shfl_xor_sync(~0u, p, o);
        if (lane == 0) hred[k][w] = p;
    }
    __syncthreads();
    if (tid < TOPK) {
        float s = 0.f;
#pragma unroll
        for (int w2 = 0; w2 < 8; w2++) s += hred[tid][w2];
        hk[tid] = s * sZ[tid];
    }
    __syncthreads();
    float4 o = make_float4(0.f, 0.f, 0.f, 0.f);
#pragma unroll
    for (int k = 0; k < TOPK; k++) {
        const float4 vv = *(const float4 *)(g_V + (size_t)srow[k] * DDIM + tid * 4);
        const float c = hk[k];
        o.x += c * vv.x; o.y += c * vv.y; o.z += c * vv.z; o.w += c * vv.w;
    }
    const float4 g4 = *(const float4 *)(gamma + tid * 4);
    o.x *= g4.x; o.y *= g4.y; o.z *= g4.z; o.w *= g4.w;
    *(float4 *)(out + (size_t)n * DDIM + tid * 4) = o;
}

// ===================== launch =====================
extern "C" void kernel_launch(void *const *d_in, const int *in_sizes, int n_in,
                              void *d_out, int out_size) {
    (void)in_sizes; (void)n_in; (void)out_size;
    const float *x     = (const float *)d_in[0];
    const float *W1    = (const float *)d_in[1];
    const float *W2    = (const float *)d_in[2];
    const float *ln_g  = (const float *)d_in[3];
    const float *ln_b  = (const float *)d_in[4];
    const float *rW    = (const float *)d_in[5];
    const float *rb    = (const float *)d_in[6];
    const float *rU    = (const float *)d_in[7];
    const float *rV    = (const float *)d_in[8];
    const float *gamma = (const float *)d_in[9];
    float *out = (float *)d_out;

    cudaFuncSetAttribute(gemm_mma<0>, cudaFuncAttributeMaxDynamicSharedMemorySize, GEMM_SMEM);
    cudaFuncSetAttribute(gemm_mma<2>, cudaFuncAttributeMaxDynamicSharedMemorySize, GEMM_SMEM);

    void *p;
    cudaGetSymbolAddress(&p, g_xhi);  __nv_bfloat16 *xhi = (__nv_bfloat16 *)p;
    cudaGetSymbolAddress(&p, g_xlo);  __nv_bfloat16 *xlo = (__nv_bfloat16 *)p;
    cudaGetSymbolAddress(&p, g_w1hi); __nv_bfloat16 *w1hi = (__nv_bfloat16 *)p;
    cudaGetSymbolAddress(&p, g_w1lo); __nv_bfloat16 *w1lo = (__nv_bfloat16 *)p;
    cudaGetSymbolAddress(&p, g_w2hi); __nv_bfloat16 *w2hi = (__nv_bfloat16 *)p;
    cudaGetSymbolAddress(&p, g_w2lo); __nv_bfloat16 *w2lo = (__nv_bfloat16 *)p;
    cudaGetSymbolAddress(&p, g_Hhi);  __nv_bfloat16 *Hhi = (__nv_bfloat16 *)p;
    cudaGetSymbolAddress(&p, g_Hlo);  __nv_bfloat16 *Hlo = (__nv_bfloat16 *)p;
    cudaGetSymbolAddress(&p, g_ln);   float *pln = (float *)p;
    cudaGetSymbolAddress(&p, g_alpha); float *alpha = (float *)p;

    // splits for MLP operands
    split_kernel<<<(N_TOK * DDIM) / 1024, 256>>>(x, xhi, xlo);
    split_kernel<<<(HDIM * DDIM) / 1024, 256>>>(W1, w1hi, w1lo);
    split_kernel<<<(DDIM * HDIM) / 1024, 256>>>(W2, w2hi, w2lo);

    // router path (exact fp32 SGEMM)
    ln_kernel<<<N_TOK, 256>>>(x, ln_g, ln_b, pln);
    unit_kernel<<<2 * NB, 256>>>(rU, rV);
    router_gemm<<<dim3(NB / 128, N_TOK / 128), 256>>>(pln, rW, rb, alpha, NB, DDIM);
    topk_kernel<<<N_TOK / 8, 256>>>();
    dyn_kernel<<<N_TOK, 256>>>(x, gamma, out);  // out = gamma * dyn

    // static path on mma.sync tensor cores (gemm2 accumulates onto dyn in out)
    gemm_mma<0><<<dim3(HDIM / 128, N_TOK / 128), 256, GEMM_SMEM>>>(
        xhi, xlo, w1hi, w1lo, nullptr, Hhi, Hlo, DDIM, HDIM);
    gemm_mma<2><<<dim3(DDIM / 128, N_TOK / 128), 256, GEMM_SMEM>>>(
        Hhi, Hlo, w2hi, w2lo, out, nullptr, nullptr, HDIM, DDIM);
}

// round 13
// speedup vs baseline: 2.0675x; 1.2885x over previous
#include <cuda_runtime.h>
#include <cuda_fp16.h>
#include <cstdint>

#define N_TOK 8192
#define DDIM  1024
#define NB    512
#define HDIM  4096
#define TOPK  8

// ===================== scratch (static device allocations) =====================
static __device__ __half g_xhi[(size_t)N_TOK * DDIM];
static __device__ __half g_xlo[(size_t)N_TOK * DDIM];
static __device__ __half g_w1[(size_t)HDIM * DDIM];
static __device__ __half g_w2[(size_t)DDIM * HDIM];
static __device__ __half g_Hhi[(size_t)N_TOK * HDIM];
static __device__ __half g_Hlo[(size_t)N_TOK * HDIM];
static __device__ float g_ln[(size_t)N_TOK * DDIM];
static __device__ float g_alpha[(size_t)N_TOK * NB];
static __device__ float g_U[(size_t)NB * DDIM];
static __device__ float g_V[(size_t)NB * DDIM];
static __device__ int   g_idx[(size_t)N_TOK * TOPK];
static __device__ float g_Z[(size_t)N_TOK * TOPK];

// ===================== sm_80-era primitives (valid on base sm_103 target) =====
__device__ __forceinline__ uint32_t smem_u32(const void *p) {
    uint32_t a;
    asm("{ .reg .u64 t; cvta.to.shared.u64 t, %1; cvt.u32.u64 %0, t; }" : "=r"(a) : "l"(p));
    return a;
}
__device__ __forceinline__ void cp_async16(uint32_t smem, const void *gmem) {
    asm volatile("cp.async.cg.shared.global [%0], [%1], 16;" :: "r"(smem), "l"(gmem)
                 : "memory");
}
__device__ __forceinline__ void cp_commit() {
    asm volatile("cp.async.commit_group;" ::: "memory");
}
template <int N>
__device__ __forceinline__ void cp_wait() {
    asm volatile("cp.async.wait_group %0;" :: "n"(N) : "memory");
}
__device__ __forceinline__ void ldm_x4(uint32_t *r, uint32_t addr) {
    asm volatile("ldmatrix.sync.aligned.m8n8.x4.shared.b16 {%0,%1,%2,%3}, [%4];"
                 : "=r"(r[0]), "=r"(r[1]), "=r"(r[2]), "=r"(r[3]) : "r"(addr));
}
__device__ __forceinline__ void mma16816(float *c, const uint32_t *a, uint32_t b0,
                                         uint32_t b1) {
    asm volatile(
        "mma.sync.aligned.m16n8k16.row.col.f32.f16.f16.f32 "
        "{%0,%1,%2,%3}, {%4,%5,%6,%7}, {%8,%9}, {%0,%1,%2,%3};"
        : "+f"(c[0]), "+f"(c[1]), "+f"(c[2]), "+f"(c[3])
        : "r"(a[0]), "r"(a[1]), "r"(a[2]), "r"(a[3]), "r"(b0), "r"(b1));
}

// SMEM geometry: per operand tile 128 rows x 32 fp16, rows padded to 80 bytes.
// 80B stride => ldmatrix 8-address phases sweep all 32 banks: conflict-free.
#define ROWB       80
#define OP_BYTES   (128 * ROWB)        // 10240
#define STG_BYTES  (3 * OP_BYTES)      // 30720 (Ahi, Alo, B)
#define GEMM_SMEM  (2 * STG_BYTES)     // 61440, double-buffered

// ===================== mma.sync GEMM (NT, K-major), 128x128 tile, k-chunk 32
// 2-product fp16 split: C = Ahi*B + Alo*B  (fp32 register accumulate)
//   A split to fp16 hi+lo (captures A to ~2^-21); B rounded to fp16 (error ~2^-11).
// EPI: 0 = GELU -> split fp16 store (OHi/OLo)    (GEMM1)
//      2 = Cout += D                             (GEMM2)
template <int EPI>
__global__ __launch_bounds__(256, 2)
void gemm_mma(const __half *__restrict__ Ahi, const __half *__restrict__ Alo,
              const __half *__restrict__ B, float *__restrict__ Cout,
              __half *__restrict__ OHi, __half *__restrict__ OLo,
              int K, int ldc) {
    extern __shared__ __align__(1024) char smem[];
    const uint32_t sbase = smem_u32(smem);

    const int tid = threadIdx.x;
    const int wid = tid >> 5, lane = tid & 31;
    const int wm = wid & 1, wn = wid >> 1;          // 2 x 4 warp grid
    const int bm = blockIdx.y * 128, bn = blockIdx.x * 128;

    const __half *srcs[3] = {Ahi + (size_t)bm * K, Alo + (size_t)bm * K,
                             B + (size_t)bn * K};

    // per-stage global->smem: each thread moves 2 x 16B per operand
    const int c0r = tid >> 2, c0k = tid & 3;          // chunk id tid
    const int c1r = (tid + 256) >> 2, c1k = tid & 3;  // chunk id tid+256
    auto load_stage = [&](int kc, int buf) {
        const uint32_t sb = sbase + buf * STG_BYTES;
#pragma unroll
        for (int t = 0; t < 3; t++) {
            cp_async16(sb + t * OP_BYTES + c0r * ROWB + c0k * 16,
                       srcs[t] + (size_t)c0r * K + kc + c0k * 8);
            cp_async16(sb + t * OP_BYTES + c1r * ROWB + c1k * 16,
                       srcs[t] + (size_t)c1r * K + kc + c1k * 8);
        }
        cp_commit();
    };

    const int lrow = lane & 15;
    const uint32_t lkoff = (uint32_t)(lane >> 4) * 16;  // +8 fp16 in k

    float acc[4][4][4];
#pragma unroll
    for (int mi = 0; mi < 4; mi++)
#pragma unroll
        for (int ni = 0; ni < 4; ni++)
#pragma unroll
            for (int j = 0; j < 4; j++) acc[mi][ni][j] = 0.f;

    const int S = K >> 5;
    load_stage(0, 0);

    for (int s = 0; s < S; s++) {
        if (s + 1 < S) { load_stage((s + 1) << 5, (s + 1) & 1); cp_wait<1>(); }
        else           { cp_wait<0>(); }
        __syncthreads();

        const uint32_t sb = sbase + (s & 1) * STG_BYTES;
        const uint32_t aHiB = sb + 0 * OP_BYTES + (wm * 64 + lrow) * ROWB + lkoff;
        const uint32_t aLoB = sb + 1 * OP_BYTES + (wm * 64 + lrow) * ROWB + lkoff;
        const uint32_t bB   = sb + 2 * OP_BYTES + (wn * 32 + lrow) * ROWB + lkoff;

#pragma unroll
        for (int ks = 0; ks < 2; ks++) {
            const uint32_t ko = ks * 32;  // 16 fp16 = 32 bytes
            uint32_t bf[2][4];
            ldm_x4(bf[0], bB + ko);             // n 0..15
            ldm_x4(bf[1], bB + 16 * ROWB + ko); // n 16..31
#pragma unroll
            for (int mi = 0; mi < 4; mi++) {
                uint32_t a[4];
                ldm_x4(a, aHiB + mi * 16 * ROWB + ko);
#pragma unroll
                for (int ni = 0; ni < 4; ni++)
                    mma16816(acc[mi][ni], a, bf[ni >> 1][ni & 1], bf[ni >> 1][(ni & 1) + 2]);
                ldm_x4(a, aLoB + mi * 16 * ROWB + ko);
#pragma unroll
                for (int ni = 0; ni < 4; ni++)
                    mma16816(acc[mi][ni], a, bf[ni >> 1][ni & 1], bf[ni >> 1][(ni & 1) + 2]);
            }
        }
        __syncthreads();
    }

    // ===== epilogue: frag (mi,ni): rows g, g+8; cols tg*2, tg*2+1 =====
    const int g = lane >> 2, tg = lane & 3;
#pragma unroll
    for (int mi = 0; mi < 4; mi++) {
#pragma unroll
        for (int ni = 0; ni < 4; ni++) {
            const int r0 = bm + wm * 64 + mi * 16 + g;
            const int r1 = r0 + 8;
            const int col = bn + wn * 32 + ni * 8 + tg * 2;
            float *c = acc[mi][ni];
            if (EPI == 0) {
#pragma unroll
                for (int pair = 0; pair < 2; pair++) {
                    const int row = pair ? r1 : r0;
                    float v0 = c[pair * 2], v1 = c[pair * 2 + 1];
                    float g0 = 0.5f * v0 * (1.0f + erff(v0 * 0.7071067811865476f));
                    float g1 = 0.5f * v1 * (1.0f + erff(v1 * 0.7071067811865476f));
                    __half h0 = __float2half_rn(g0);
                    __half h1 = __float2half_rn(g1);
                    __half2 hh; hh.x = h0; hh.y = h1;
                    *(__half2 *)(OHi + (size_t)row * ldc + col) = hh;
                    *(__half2 *)(OLo + (size_t)row * ldc + col) =
                        __floats2half2_rn(g0 - __half2float(h0), g1 - __half2float(h1));
                }
            } else {
                float2 o0 = *(float2 *)(Cout + (size_t)r0 * ldc + col);
                float2 o1 = *(float2 *)(Cout + (size_t)r1 * ldc + col);
                o0.x += c[0]; o0.y += c[1];
                o1.x += c[2]; o1.y += c[3];
                *(float2 *)(Cout + (size_t)r0 * ldc + col) = o0;
                *(float2 *)(Cout + (size_t)r1 * ldc + col) = o1;
            }
        }
    }
}

// ===================== f32x2 SGEMM for router (proven round-2 path) =====================
__device__ __forceinline__ unsigned long long pack2(float a, float b) {
    unsigned long long r;
    asm("mov.b64 %0, {%1,%2};" : "=l"(r) : "f"(a), "f"(b));
    return r;
}
__device__ __forceinline__ void unpack2(unsigned long long v, float &a, float &b) {
    asm("mov.b64 {%0,%1}, %2;" : "=f"(a), "=f"(b) : "l"(v));
}
__device__ __forceinline__ void ffma2(unsigned long long &d, unsigned long long a,
                                      unsigned long long b) {
    asm("fma.rn.f32x2 %0, %1, %2, %0;" : "+l"(d) : "l"(a), "l"(b));
}

__global__ __launch_bounds__(256, 2)
void router_gemm(const float *__restrict__ A, const float *__restrict__ B,
                 const float *__restrict__ bias, float *__restrict__ C,
                 int N, int K) {
    __shared__ float As[16][128];
    __shared__ float Bs[16][128];
    const int tid = threadIdx.x;
    const int tx = tid & 15;
    const int ty = tid >> 4;
    const int bm = blockIdx.y * 128;
    const int bn = blockIdx.x * 128;
    const int lr = tid >> 2;
    const int lc = (tid & 3) << 2;

    const float *Ap = A + (size_t)(bm + lr) * K + lc;
    const float *Bp = B + (size_t)(bn + lr) * K + lc;

    unsigned long long acc[8][4];
#pragma unroll
    for (int i = 0; i < 8; i++)
#pragma unroll
        for (int j = 0; j < 4; j++) acc[i][j] = 0ULL;

    for (int kt = 0; kt < K; kt += 16) {
        float4 a0 = *(const float4 *)Ap;
        float4 a1 = *(const float4 *)(Ap + (size_t)64 * K);
        float4 b0 = *(const float4 *)Bp;
        float4 b1 = *(const float4 *)(Bp + (size_t)64 * K);
        As[lc + 0][lr] = a0.x; As[lc + 1][lr] = a0.y; As[lc + 2][lr] = a0.z; As[lc + 3][lr] = a0.w;
        As[lc + 0][lr + 64] = a1.x; As[lc + 1][lr + 64] = a1.y; As[lc + 2][lr + 64] = a1.z; As[lc + 3][lr + 64] = a1.w;
        Bs[lc + 0][lr] = b0.x; Bs[lc + 1][lr] = b0.y; Bs[lc + 2][lr] = b0.z; Bs[lc + 3][lr] = b0.w;
        Bs[lc + 0][lr + 64] = b1.x; Bs[lc + 1][lr + 64] = b1.y; Bs[lc + 2][lr + 64] = b1.z; Bs[lc + 3][lr + 64] = b1.w;
        __syncthreads();
#pragma unroll
        for (int kk = 0; kk < 16; kk++) {
            ulonglong2 bv0 = *reinterpret_cast<const ulonglong2 *>(&Bs[kk][tx * 4]);
            ulonglong2 bv1 = *reinterpret_cast<const ulonglong2 *>(&Bs[kk][64 + tx * 4]);
            float4 m0 = *reinterpret_cast<const float4 *>(&As[kk][ty * 8]);
            float4 m1 = *reinterpret_cast<const float4 *>(&As[kk][ty * 8 + 4]);
            float mr[8] = {m0.x, m0.y, m0.z, m0.w, m1.x, m1.y, m1.z, m1.w};
#pragma unroll
            for (int i = 0; i < 8; i++) {
                unsigned long long a2 = pack2(mr[i], mr[i]);
                ffma2(acc[i][0], a2, bv0.x);
                ffma2(acc[i][1], a2, bv0.y);
                ffma2(acc[i][2], a2, bv1.x);
                ffma2(acc[i][3], a2, bv1.y);
            }
        }
        __syncthreads();
        Ap += 16;
        Bp += 16;
    }

#pragma unroll
    for (int i = 0; i < 8; i++) {
        float v[8];
        unpack2(acc[i][0], v[0], v[1]);
        unpack2(acc[i][1], v[2], v[3]);
        unpack2(acc[i][2], v[4], v[5]);
        unpack2(acc[i][3], v[6], v[7]);
        const int row = bm + ty * 8 + i;
        const int c0 = bn + tx * 4;
        const int c1 = bn + 64 + tx * 4;
#pragma unroll
        for (int j = 0; j < 8; j++) {
            int col = (j < 4) ? (c0 + j) : (c1 + (j - 4));
            float r = v[j] + bias[col];
            r = fminf(fmaxf(r, -10.0f), 10.0f);
            v[j] = fmaxf(r, 0.0f) + log1pf(expf(-fabsf(r)));  // stable softplus
        }
        *(float4 *)(C + (size_t)row * N + c0) = make_float4(v[0], v[1], v[2], v[3]);
        *(float4 *)(C + (size_t)row * N + c1) = make_float4(v[4], v[5], v[6], v[7]);
    }
}

// ===================== fp32 -> (hi, lo) fp16 split =====================
__global__ __launch_bounds__(256)
void split2_kernel(const float *__restrict__ in, __half *__restrict__ hi,
                   __half *__restrict__ lo) {
    const size_t i4 = (size_t)blockIdx.x * 256 + threadIdx.x;
    const float4 v = *(const float4 *)(in + i4 * 4);
    __half h0 = __float2half_rn(v.x), h1 = __float2half_rn(v.y);
    __half h2 = __float2half_rn(v.z), h3 = __float2half_rn(v.w);
    __half2 a, b;
    a.x = h0; a.y = h1; b.x = h2; b.y = h3;
    *(__half2 *)(hi + i4 * 4) = a;
    *(__half2 *)(hi + i4 * 4 + 2) = b;
    *(__half2 *)(lo + i4 * 4) =
        __floats2half2_rn(v.x - __half2float(h0), v.y - __half2float(h1));
    *(__half2 *)(lo + i4 * 4 + 2) =
        __floats2half2_rn(v.z - __half2float(h2), v.w - __half2float(h3));
}

// ===================== fp32 -> fp16 round (weights) =====================
__global__ __launch_bounds__(256)
void round_kernel(const float *__restrict__ in, __half *__restrict__ out) {
    const size_t i4 = (size_t)blockIdx.x * 256 + threadIdx.x;
    const float4 v = *(const float4 *)(in + i4 * 4);
    __half2 a, b;
    a = __floats2half2_rn(v.x, v.y);
    b = __floats2half2_rn(v.z, v.w);
    *(__half2 *)(out + i4 * 4) = a;
    *(__half2 *)(out + i4 * 4 + 2) = b;
}

// ===================== LayerNorm (fp32 out, feeds router SGEMM) =====================
__global__ __launch_bounds__(256)
void ln_kernel(const float *__restrict__ x, const float *__restrict__ g,
               const float *__restrict__ b, float *__restrict__ out) {
    __shared__ float sm1[8], sm2[8];
    const int n = blockIdx.x, tid = threadIdx.x;
    const float4 xr = *(const float4 *)(x + (size_t)n * DDIM + tid * 4);
    float s = xr.x + xr.y + xr.z + xr.w;
    float s2 = xr.x * xr.x + xr.y * xr.y + xr.z * xr.z + xr.w * xr.w;
    const int lane = tid & 31, w = tid >> 5;
#pragma unroll
    for (int o = 16; o; o >>= 1) {
        s += __shfl_xor_sync(~0u, s, o);
        s2 += __shfl_xor_sync(~0u, s2, o);
    }
    if (lane == 0) { sm1[w] = s; sm2[w] = s2; }
    __syncthreads();
    float ts = 0.f, ts2 = 0.f;
#pragma unroll
    for (int i = 0; i < 8; i++) { ts += sm1[i]; ts2 += sm2[i]; }
    const float mu = ts * (1.0f / DDIM);
    const float var = ts2 * (1.0f / DDIM) - mu * mu;
    const float rstd = rsqrtf(var + 1e-5f);
    const float4 g4 = *(const float4 *)(g + tid * 4);
    const float4 b4 = *(const float4 *)(b + tid * 4);
    float4 o;
    o.x = (xr.x - mu) * rstd * g4.x + b4.x;
    o.y = (xr.y - mu) * rstd * g4.y + b4.y;
    o.z = (xr.z - mu) * rstd * g4.z + b4.z;
    o.w = (xr.w - mu) * rstd * g4.w + b4.w;
    *(float4 *)(out + (size_t)n * DDIM + tid * 4) = o;
}

// ===================== unit-normalize U and V rows =====================
__global__ __launch_bounds__(256)
void unit_kernel(const float *__restrict__ rU, const float *__restrict__ rV) {
    __shared__ float sm[8];
    const int r = blockIdx.x, tid = threadIdx.x;
    const float *src;
    float *dst;
    if (r < NB) { src = rU + (size_t)r * DDIM; dst = g_U + (size_t)r * DDIM; }
    else        { src = rV + (size_t)(r - NB) * DDIM; dst = g_V + (size_t)(r - NB) * DDIM; }
    const float4 xr = *(const float4 *)(src + tid * 4);
    float s2 = xr.x * xr.x + xr.y * xr.y + xr.z * xr.z + xr.w * xr.w;
    const int lane = tid & 31, w = tid >> 5;
#pragma unroll
    for (int o = 16; o; o >>= 1) s2 += __shfl_xor_sync(~0u, s2, o);
    if (lane == 0) sm[w] = s2;
    __syncthreads();
    float t = 0.f;
#pragma unroll
    for (int i = 0; i < 8; i++) t += sm[i];
    const float sc = 1.0f / fmaxf(sqrtf(t), 1e-6f);
    float4 o;
    o.x = xr.x * sc; o.y = xr.y * sc; o.z = xr.z * sc; o.w = xr.w * sc;
    *(float4 *)(dst + tid * 4) = o;
}

// ===================== top-8 + Z =====================
__global__ __launch_bounds__(256)
void topk_kernel() {
    const int warp = (blockIdx.x * blockDim.x + threadIdx.x) >> 5;
    const int lane = threadIdx.x & 31;
    const float *a = g_alpha + (size_t)warp * NB;
    float v[16];
#pragma unroll
    for (int s = 0; s < 16; s++) v[s] = a[lane + 32 * s];
    float phi[TOPK];
    int pid[TOPK];
    float S = 0.f;
#pragma unroll
    for (int k = 0; k < TOPK; k++) {
        float bv = -1e30f;
        int bi = 0;
#pragma unroll
        for (int s = 0; s < 16; s++) {
            int id = lane + 32 * s;
            if (v[s] > bv) { bv = v[s]; bi = id; }
        }
#pragma unroll
        for (int off = 16; off; off >>= 1) {
            float ov = __shfl_xor_sync(~0u, bv, off);
            int oi = __shfl_xor_sync(~0u, bi, off);
            if (ov > bv || (ov == bv && oi < bi)) { bv = ov; bi = oi; }
        }
        phi[k] = bv;
        pid[k] = bi;
        S += bv;
        if ((bi & 31) == lane) {
            const int slot = bi >> 5;
#pragma unroll
            for (int s = 0; s < 16; s++)
                if (s == slot) v[s] = -1e30f;
        }
    }
    const float t = tanhf(S);
    const float inv = 1.0f / (S + 1e-6f);
    if (lane == 0) {
#pragma unroll
        for (int k = 0; k < TOPK; k++) {
            g_Z[(size_t)warp * TOPK + k] = phi[k] * inv * t;
            g_idx[(size_t)warp * TOPK + k] = pid[k];
        }
    }
}

// ===================== dynamic path (writes gamma*dyn into out) =====================
__global__ __launch_bounds__(256)
void dyn_kernel(const float *__restrict__ x, const float *__restrict__ gamma,
                float *__restrict__ out) {
    __shared__ int srow[TOPK];
    __shared__ float sZ[TOPK];
    __shared__ float hred[TOPK][8];
    __shared__ float hk[TOPK];
    const int n = blockIdx.x, tid = threadIdx.x;
    if (tid < TOPK) {
        srow[tid] = g_idx[(size_t)n * TOPK + tid];
        sZ[tid] = g_Z[(size_t)n * TOPK + tid];
    }
    __syncthreads();
    const float4 xr = *(const float4 *)(x + (size_t)n * DDIM + tid * 4);
    const int lane = tid & 31, w = tid >> 5;
#pragma unroll
    for (int k = 0; k < TOPK; k++) {
        const float4 u = *(const float4 *)(g_U + (size_t)srow[k] * DDIM + tid * 4);
        float p = xr.x * u.x + xr.y * u.y + xr.z * u.z + xr.w * u.w;
#pragma unroll
        for (int o = 16; o; o >>= 1) p += __shfl_xor_sync(~0u, p, o);
        if (lane == 0) hred[k][w] = p;
    }
    __syncthreads();
    if (tid < TOPK) {
        float s = 0.f;
#pragma unroll
        for (int w2 = 0; w2 < 8; w2++) s += hred[tid][w2];
        hk[tid] = s * sZ[tid];
    }
    __syncthreads();
    float4 o = make_float4(0.f, 0.f, 0.f, 0.f);
#pragma unroll
    for (int k = 0; k < TOPK; k++) {
        const float4 vv = *(const float4 *)(g_V + (size_t)srow[k] * DDIM + tid * 4);
        const float c = hk[k];
        o.x += c * vv.x; o.y += c * vv.y; o.z += c * vv.z; o.w += c * vv.w;
    }
    const float4 g4 = *(const float4 *)(gamma + tid * 4);
    o.x *= g4.x; o.y *= g4.y; o.z *= g4.z; o.w *= g4.w;
    *(float4 *)(out + (size_t)n * DDIM + tid * 4) = o;
}

// ===================== launch =====================
extern "C" void kernel_launch(void *const *d_in, const int *in_sizes, int n_in,
                              void *d_out, int out_size) {
    (void)in_sizes; (void)n_in; (void)out_size;
    const float *x     = (const float *)d_in[0];
    const float *W1    = (const float *)d_in[1];
    const float *W2    = (const float *)d_in[2];
    const float *ln_g  = (const float *)d_in[3];
    const float *ln_b  = (const float *)d_in[4];
    const float *rW    = (const float *)d_in[5];
    const float *rb    = (const float *)d_in[6];
    const float *rU    = (const float *)d_in[7];
    const float *rV    = (const float *)d_in[8];
    const float *gamma = (const float *)d_in[9];
    float *out = (float *)d_out;

    cudaFuncSetAttribute(gemm_mma<0>, cudaFuncAttributeMaxDynamicSharedMemorySize, GEMM_SMEM);
    cudaFuncSetAttribute(gemm_mma<2>, cudaFuncAttributeMaxDynamicSharedMemorySize, GEMM_SMEM);

    void *p;
    cudaGetSymbolAddress(&p, g_xhi);  __half *xhi = (__half *)p;
    cudaGetSymbolAddress(&p, g_xlo);  __half *xlo = (__half *)p;
    cudaGetSymbolAddress(&p, g_w1);   __half *w1h = (__half *)p;
    cudaGetSymbolAddress(&p, g_w2);   __half *w2h = (__half *)p;
    cudaGetSymbolAddress(&p, g_Hhi);  __half *Hhi = (__half *)p;
    cudaGetSymbolAddress(&p, g_Hlo);  __half *Hlo = (__half *)p;
    cudaGetSymbolAddress(&p, g_ln);   float *pln = (float *)p;
    cudaGetSymbolAddress(&p, g_alpha); float *alpha = (float *)p;

    // conversions for MLP operands (launch indices 0..2)
    split2_kernel<<<(N_TOK * DDIM) / 1024, 256>>>(x, xhi, xlo);
    round_kernel<<<(HDIM * DDIM) / 1024, 256>>>(W1, w1h);
    round_kernel<<<(DDIM * HDIM) / 1024, 256>>>(W2, w2h);

    // GEMM1 at launch index 3 -> the slot ncu samples (observed R2/R10)
    gemm_mma<0><<<dim3(HDIM / 128, N_TOK / 128), 256, GEMM_SMEM>>>(
        xhi, xlo, w1h, nullptr, Hhi, Hlo, DDIM, HDIM);

    // router path (exact fp32 SGEMM)
    ln_kernel<<<N_TOK, 256>>>(x, ln_g, ln_b, pln);
    unit_kernel<<<2 * NB, 256>>>(rU, rV);
    router_gemm<<<dim3(NB / 128, N_TOK / 128), 256>>>(pln, rW, rb, alpha, NB, DDIM);
    topk_kernel<<<N_TOK / 8, 256>>>();
    dyn_kernel<<<N_TOK, 256>>>(x, gamma, out);  // out = gamma * dyn

    // GEMM2 accumulates static path onto dyn in out
    gemm_mma<2><<<dim3(DDIM / 128, N_TOK / 128), 256, GEMM_SMEM>>>(
        Hhi, Hlo, w2h, out, nullptr, nullptr, HDIM, DDIM);
}